// round 2
// baseline (speedup 1.0000x reference)
#include <cuda_runtime.h>
#include <math.h>

// Problem constants
#define BB 32
#define CC 64
#define VV 1024
#define TT 24
#define COUT 64
#define MROWS (BB*CC)            // 2048
#define PART ((size_t)MROWS*VV)  // 2,097,152 floats per (B*C, V) plane
#define CVSZ (CC*VV)             // 65536

// Scratch (static device memory; allocation-free at runtime)
__device__ __align__(128) float g_xT[(size_t)TT*MROWS*VV];   // [t][b*C+c][v]
__device__ __align__(128) float g_ys[(size_t)TT*MROWS*VV];   // hy per step; ys[t] is h for t+1
__device__ __align__(128) float g_G[3*(size_t)MROWS*VV];     // [comb | x1 | x2]
__device__ __align__(128) float g_c[(size_t)MROWS*VV];       // cell state

__device__ __forceinline__ float sigf(float x) { return 1.0f / (1.0f + __expf(-x)); }

// ---------------------------------------------------------------------------
// Transpose x: (B,C,V,T) -> xT (T, B*C, V).
__global__ void transpose_x(const float* __restrict__ x) {
    __shared__ float tile[32][25];
    int r  = blockIdx.x;
    int v0 = blockIdx.y * 32;
    const float* src = x + ((size_t)r * VV + v0) * TT;
    for (int i = threadIdx.x; i < 32 * TT; i += blockDim.x) {
        int v = i / TT, t = i % TT;
        tile[v][t] = src[i];
    }
    __syncthreads();
    for (int i = threadIdx.x; i < 32 * TT; i += blockDim.x) {
        int t = i / 32, v = i % 32;
        g_xT[(size_t)t * PART + (size_t)r * VV + v0 + v] = tile[v][t];
    }
}

__global__ void zero_c() {
    size_t i = (size_t)blockIdx.x * blockDim.x + threadIdx.x;
    g_c[i] = 0.0f;
}

// ---------------------------------------------------------------------------
// Hop SGEMM: C(2048x1024) = (Aop [+ Hop]) @ Bmat(1024x1024)
// Tile 128(M) x 64(N), BK=8, 256 threads, 8x4 microtile. 256 CTAs.
// If combOut != nullptr, bx==0 CTAs also store the (A+H) operand (= comb).
#define APAD 132
#define BPAD 68
__global__ __launch_bounds__(256) void sgemm_hop(
    const float* __restrict__ Aop, const float* __restrict__ Hop,
    const float* __restrict__ Bmat, float* __restrict__ Cop,
    float* __restrict__ combOut, int addH)
{
    __shared__ float As[8 * APAD];   // [k][128] stride 132 (conflict-free, f4-aligned)
    __shared__ float Bs[8 * BPAD];   // [k][64]  stride 68

    int tid = threadIdx.x;
    int bx = blockIdx.x, by = blockIdx.y;

    int aRow = tid >> 1;            // 0..127
    int aCol = (tid & 1) * 4;       // 0 or 4
    size_t aOff = (size_t)(by * 128 + aRow) * 1024 + aCol;

    int bRow = tid >> 4;            // 0..15 (only tid<128 used -> 0..7)
    int bCol = (tid & 15) * 4;
    const float* Bp = Bmat + bx * 64;

    int tRow = (tid >> 4) * 8;      // 0..120
    int tCol = (tid & 15) * 4;      // 0..60

    float acc[8][4];
    #pragma unroll
    for (int i = 0; i < 8; i++)
        #pragma unroll
        for (int j = 0; j < 4; j++) acc[i][j] = 0.f;

    // prefetch k0 = 0
    float4 a4 = *reinterpret_cast<const float4*>(Aop + aOff);
    if (addH) {
        float4 h4 = *reinterpret_cast<const float4*>(Hop + aOff);
        a4.x += h4.x; a4.y += h4.y; a4.z += h4.z; a4.w += h4.w;
    }
    float4 b4 = make_float4(0.f, 0.f, 0.f, 0.f);
    if (tid < 128)
        b4 = *reinterpret_cast<const float4*>(Bp + (size_t)bRow * 1024 + bCol);

    for (int k0 = 0; k0 < 1024; k0 += 8) {
        As[(aCol + 0) * APAD + aRow] = a4.x;
        As[(aCol + 1) * APAD + aRow] = a4.y;
        As[(aCol + 2) * APAD + aRow] = a4.z;
        As[(aCol + 3) * APAD + aRow] = a4.w;
        if (tid < 128)
            *reinterpret_cast<float4*>(&Bs[bRow * BPAD + bCol]) = b4;
        if (combOut != nullptr && bx == 0)
            *reinterpret_cast<float4*>(combOut + aOff + k0) = a4;
        __syncthreads();

        if (k0 + 8 < 1024) {
            a4 = *reinterpret_cast<const float4*>(Aop + aOff + k0 + 8);
            if (addH) {
                float4 h4 = *reinterpret_cast<const float4*>(Hop + aOff + k0 + 8);
                a4.x += h4.x; a4.y += h4.y; a4.z += h4.z; a4.w += h4.w;
            }
            if (tid < 128)
                b4 = *reinterpret_cast<const float4*>(Bp + (size_t)(k0 + 8 + bRow) * 1024 + bCol);
        }

        #pragma unroll
        for (int k = 0; k < 8; k++) {
            float regM[8];
            #pragma unroll
            for (int i = 0; i < 8; i++) regM[i] = As[k * APAD + tRow + i];
            float4 rn = *reinterpret_cast<const float4*>(&Bs[k * BPAD + tCol]);
            float regN[4] = {rn.x, rn.y, rn.z, rn.w};
            #pragma unroll
            for (int i = 0; i < 8; i++)
                #pragma unroll
                for (int j = 0; j < 4; j++) acc[i][j] += regM[i] * regN[j];
        }
        __syncthreads();
    }

    float* Cp = Cop + (size_t)(by * 128 + tRow) * 1024 + bx * 64 + tCol;
    #pragma unroll
    for (int i = 0; i < 8; i++) {
        float4 o = make_float4(acc[i][0], acc[i][1], acc[i][2], acc[i][3]);
        *reinterpret_cast<float4*>(Cp + (size_t)i * 1024) = o;
    }
}

// ---------------------------------------------------------------------------
// Fused gate GEMM + LSTM pointwise.
// Per batch b, v-strip of 64: gates(256 x 64) = W(256x192) @ Gb(192x64) + bias,
// then LSTM in registers. Thread microtile rows = {i,f,cell,o} x {c0, c0+1}.
#define WPAD 260
__global__ __launch_bounds__(256, 2) void gate_lstm(
    const float* __restrict__ W, const float* __restrict__ bias,
    float* __restrict__ ysOut)
{
    __shared__ float As[8 * WPAD];   // [k][256] stride 260
    __shared__ float Bs[8 * BPAD];   // [k][64]  stride 68

    int tid = threadIdx.x;
    int bx = blockIdx.x;             // v-strip (16)
    int b  = blockIdx.y;             // batch (32)

    const float* Wrow = W + (size_t)tid * 192;

    int bRow = tid >> 4;             // 0..7 for tid<128
    int bCol = (tid & 15) * 4;

    int c0   = (tid >> 3) * 2;       // channel pair base: 0,2,...,62
    int tCol = (tid & 7) * 8;        // 0..56

    float acc[8][8];                 // [g*2+p][j]
    #pragma unroll
    for (int r = 0; r < 8; r++)
        #pragma unroll
        for (int j = 0; j < 8; j++) acc[r][j] = 0.f;

    auto rowptr = [&](int k) -> const float* {
        return g_G + (size_t)(k >> 6) * PART + (size_t)b * CVSZ +
               (size_t)(k & 63) * VV + bx * 64;
    };

    // prefetch k0 = 0
    float4 w0 = *reinterpret_cast<const float4*>(Wrow + 0);
    float4 w1 = *reinterpret_cast<const float4*>(Wrow + 4);
    float4 b4 = make_float4(0.f, 0.f, 0.f, 0.f);
    if (tid < 128)
        b4 = *reinterpret_cast<const float4*>(rowptr(bRow) + bCol);

    for (int k0 = 0; k0 < 192; k0 += 8) {
        As[0 * WPAD + tid] = w0.x;
        As[1 * WPAD + tid] = w0.y;
        As[2 * WPAD + tid] = w0.z;
        As[3 * WPAD + tid] = w0.w;
        As[4 * WPAD + tid] = w1.x;
        As[5 * WPAD + tid] = w1.y;
        As[6 * WPAD + tid] = w1.z;
        As[7 * WPAD + tid] = w1.w;
        if (tid < 128)
            *reinterpret_cast<float4*>(&Bs[bRow * BPAD + bCol]) = b4;
        __syncthreads();

        if (k0 + 8 < 192) {
            w0 = *reinterpret_cast<const float4*>(Wrow + k0 + 8);
            w1 = *reinterpret_cast<const float4*>(Wrow + k0 + 12);
            if (tid < 128)
                b4 = *reinterpret_cast<const float4*>(rowptr(k0 + 8 + bRow) + bCol);
        }

        #pragma unroll
        for (int k = 0; k < 8; k++) {
            float regM[8];
            #pragma unroll
            for (int g = 0; g < 4; g++) {
                float2 m = *reinterpret_cast<const float2*>(&As[k * WPAD + g * 64 + c0]);
                regM[g * 2 + 0] = m.x;
                regM[g * 2 + 1] = m.y;
            }
            float4 rn0 = *reinterpret_cast<const float4*>(&Bs[k * BPAD + tCol]);
            float4 rn1 = *reinterpret_cast<const float4*>(&Bs[k * BPAD + tCol + 4]);
            float regN[8] = {rn0.x, rn0.y, rn0.z, rn0.w, rn1.x, rn1.y, rn1.z, rn1.w};
            #pragma unroll
            for (int r = 0; r < 8; r++)
                #pragma unroll
                for (int j = 0; j < 8; j++) acc[r][j] += regM[r] * regN[j];
        }
        __syncthreads();
    }

    // LSTM epilogue in registers.
    #pragma unroll
    for (int p = 0; p < 2; p++) {
        int c = c0 + p;
        float bi = bias[c];
        float bf = bias[64 + c];
        float bg = bias[128 + c];
        float bo = bias[192 + c];
        size_t base = (size_t)b * CVSZ + (size_t)c * VV + bx * 64 + tCol;

        float4 cold0 = *reinterpret_cast<const float4*>(g_c + base);
        float4 cold1 = *reinterpret_cast<const float4*>(g_c + base + 4);
        float coldv[8] = {cold0.x, cold0.y, cold0.z, cold0.w,
                          cold1.x, cold1.y, cold1.z, cold1.w};
        float cy[8], hy[8];
        #pragma unroll
        for (int j = 0; j < 8; j++) {
            float ig = acc[0 * 2 + p][j] + bi;
            float fg = acc[1 * 2 + p][j] + bf;
            float gg = acc[2 * 2 + p][j] + bg;
            float og = acc[3 * 2 + p][j] + bo;
            float ccur = sigf(fg) * coldv[j] + sigf(ig) * gg;
            cy[j] = ccur;
            hy[j] = sigf(og) * tanhf(ccur);
        }
        *reinterpret_cast<float4*>(g_c + base)     = make_float4(cy[0], cy[1], cy[2], cy[3]);
        *reinterpret_cast<float4*>(g_c + base + 4) = make_float4(cy[4], cy[5], cy[6], cy[7]);
        *reinterpret_cast<float4*>(ysOut + base)     = make_float4(hy[0], hy[1], hy[2], hy[3]);
        *reinterpret_cast<float4*>(ysOut + base + 4) = make_float4(hy[4], hy[5], hy[6], hy[7]);
    }
}

// ---------------------------------------------------------------------------
// Final projection: out[b,o,v,t] = sum_c Wout[o,c]*ys[t,b,c,v] + bout[o]
__global__ __launch_bounds__(256) void proj_out(const float* __restrict__ Wout,
                                                const float* __restrict__ bout,
                                                float* __restrict__ out) {
    __shared__ float sm[TT * CC * 8];   // 48KB: [t][c][vv]
    int b  = blockIdx.y;
    int v0 = blockIdx.x * 8;
    for (int i = threadIdx.x; i < TT * CC * 8; i += 256) {
        int t = i / (CC * 8);
        int rem = i % (CC * 8);
        int c = rem >> 3, vv = rem & 7;
        sm[i] = g_ys[(size_t)t * PART + (size_t)b * CVSZ + (size_t)c * VV + v0 + vv];
    }
    __syncthreads();
    for (int p = threadIdx.x; p < COUT * 8; p += 256) {
        int o = p >> 3, vv = p & 7;
        float accp[TT];
        #pragma unroll
        for (int t = 0; t < TT; t++) accp[t] = 0.f;
        for (int c = 0; c < CC; c++) {
            float w = Wout[o * CC + c];
            #pragma unroll
            for (int t = 0; t < TT; t++) accp[t] += w * sm[t * (CC * 8) + c * 8 + vv];
        }
        float bo = bout[o];
        float* op = out + ((size_t)(b * COUT + o) * VV + v0 + vv) * TT;
        #pragma unroll
        for (int t = 0; t < TT; t++) op[t] = accp[t] + bo;
    }
}

// ---------------------------------------------------------------------------
extern "C" void kernel_launch(void* const* d_in, const int* in_sizes, int n_in,
                              void* d_out, int out_size) {
    const float* x      = (const float*)d_in[0];
    const float* Amat   = (const float*)d_in[1];
    const float* W_gout = (const float*)d_in[2];
    const float* b_gout = (const float*)d_in[3];
    const float* W_out  = (const float*)d_in[4];
    const float* b_out  = (const float*)d_in[5];
    float* out = (float*)d_out;

    float* xT = nullptr; float* ys = nullptr; float* G = nullptr;
    cudaGetSymbolAddress((void**)&xT, g_xT);
    cudaGetSymbolAddress((void**)&ys, g_ys);
    cudaGetSymbolAddress((void**)&G,  g_G);

    transpose_x<<<dim3(MROWS, VV / 32), 256>>>(x);
    zero_c<<<(MROWS * VV) / 256, 256>>>();

    dim3 hopGrid(VV / 64, MROWS / 128);        // (16, 16) = 256 CTAs
    dim3 gateGrid(VV / 64, BB);                // (16, 32) = 512 CTAs

    for (int t = 0; t < TT; t++) {
        const float* hprev = (t > 0) ? (ys + (size_t)(t - 1) * PART) : ys;
        // hop1: x1 = (x_t + h) @ A ; also writes comb into g_G part 0
        sgemm_hop<<<hopGrid, 256>>>(xT + (size_t)t * PART, hprev, Amat,
                                    G + PART, G, t > 0 ? 1 : 0);
        // hop2: x2 = x1 @ A
        sgemm_hop<<<hopGrid, 256>>>(G + PART, nullptr, Amat,
                                    G + 2 * PART, nullptr, 0);
        // gates + LSTM pointwise fused
        gate_lstm<<<gateGrid, 256>>>(W_gout, b_gout, ys + (size_t)t * PART);
    }

    proj_out<<<dim3(VV / 8, BB), 256>>>(W_out, b_out, out);
}

// round 4
// speedup vs baseline: 1.7986x; 1.7986x over previous
#include <cuda_runtime.h>
#include <cuda_bf16.h>
#include <math.h>
#include <stdint.h>

// Problem constants
#define BB 32
#define CC 64
#define VV 1024
#define TT 24
#define COUT 64
#define MROWS (BB*CC)            // 2048
#define PART ((size_t)MROWS*VV)  // 2,097,152 floats
#define CVSZ (CC*VV)             // 65536

// ---------------------------------------------------------------------------
__device__ __forceinline__ uint32_t smem_to_u32(const void* p) {
    uint32_t a;
    asm("{ .reg .u64 t; cvta.to.shared.u64 t, %1; cvt.u32.u64 %0, t; }" : "=r"(a) : "l"(p));
    return a;
}
__device__ __forceinline__ uint32_t lds32(uint32_t a) {
    uint32_t v; asm("ld.shared.b32 %0, [%1];" : "=r"(v) : "r"(a)); return v;
}
__device__ __forceinline__ void cpasync16(uint32_t dst, const void* src) {
    asm volatile("cp.async.cg.shared.global [%0], [%1], 16;" :: "r"(dst), "l"(src));
}
#define CP_COMMIT() asm volatile("cp.async.commit_group;" ::: "memory")
#define CP_WAIT(n)  asm volatile("cp.async.wait_group %0;" :: "n"(n) : "memory")

// m16n8k16 row.col bf16 -> fp32 accumulate (baseline PTX, works on sm_103)
__device__ __forceinline__ void mma16816(float* c, const uint32_t* a, const uint32_t* b) {
    asm volatile(
        "mma.sync.aligned.m16n8k16.row.col.f32.bf16.bf16.f32 "
        "{%0,%1,%2,%3}, {%4,%5,%6,%7}, {%8,%9}, {%0,%1,%2,%3};"
        : "+f"(c[0]), "+f"(c[1]), "+f"(c[2]), "+f"(c[3])
        : "r"(a[0]), "r"(a[1]), "r"(a[2]), "r"(a[3]), "r"(b[0]), "r"(b[1]));
}

__device__ __forceinline__ float sigf(float x) { return 1.0f / (1.0f + __expf(-x)); }
__device__ __forceinline__ float tanh_fast(float x) {
    float y; asm("tanh.approx.f32 %0, %1;" : "=f"(y) : "f"(x)); return y;
}
__device__ __forceinline__ uint32_t packbf2(float a, float b) {
    return ((uint32_t)__bfloat16_as_ushort(__float2bfloat16(b)) << 16) |
           (uint32_t)__bfloat16_as_ushort(__float2bfloat16(a));
}

// ---------------------------------------------------------------------------
// Scratch
__device__ __align__(128) float g_xT[(size_t)TT*MROWS*VV];
__device__ __align__(128) float g_ys[(size_t)TT*MROWS*VV];
__device__ __align__(128) float g_G[3*(size_t)MROWS*VV];   // [comb | x1 | x2] fp32
__device__ __align__(128) float g_c[(size_t)MROWS*VV];
__device__ __align__(128) __nv_bfloat16 g_combhi[(size_t)MROWS*VV];
__device__ __align__(128) __nv_bfloat16 g_comblo[(size_t)MROWS*VV];
__device__ __align__(128) __nv_bfloat16 g_x1hi[(size_t)MROWS*VV];
__device__ __align__(128) __nv_bfloat16 g_x1lo[(size_t)MROWS*VV];
__device__ __align__(128) __nv_bfloat16 g_Bhi[(size_t)VV*VV];  // A^T hi  [n][k]
__device__ __align__(128) __nv_bfloat16 g_Blo[(size_t)VV*VV];  // A^T lo  [n][k]

// ---------------------------------------------------------------------------
__global__ void transpose_x(const float* __restrict__ x) {
    __shared__ float tile[32][25];
    int r  = blockIdx.x;
    int v0 = blockIdx.y * 32;
    const float* src = x + ((size_t)r * VV + v0) * TT;
    for (int i = threadIdx.x; i < 32 * TT; i += blockDim.x) {
        int v = i / TT, t = i % TT;
        tile[v][t] = src[i];
    }
    __syncthreads();
    for (int i = threadIdx.x; i < 32 * TT; i += blockDim.x) {
        int t = i / 32, v = i % 32;
        g_xT[(size_t)t * PART + (size_t)r * VV + v0 + v] = tile[v][t];
    }
}

__global__ void zero_c() {
    size_t i = (size_t)blockIdx.x * blockDim.x + threadIdx.x;
    g_c[i] = 0.0f;
}

// Bhi/Blo[n][k] = bf16split(A[k][n])
__global__ void bsplit(const float* __restrict__ A) {
    __shared__ float tile[32][33];
    int k0 = blockIdx.x * 32, n0 = blockIdx.y * 32;
    int tx = threadIdx.x & 31, ty = threadIdx.x >> 5;
    #pragma unroll
    for (int i = 0; i < 4; i++) {
        int k = ty + i * 8;
        tile[k][tx] = A[(size_t)(k0 + k) * VV + n0 + tx];
    }
    __syncthreads();
    #pragma unroll
    for (int i = 0; i < 4; i++) {
        int n = ty + i * 8;
        float v = tile[tx][n];
        __nv_bfloat16 h = __float2bfloat16(v);
        __nv_bfloat16 l = __float2bfloat16(v - __bfloat162float(h));
        g_Bhi[(size_t)(n0 + n) * VV + k0 + tx] = h;
        g_Blo[(size_t)(n0 + n) * VV + k0 + tx] = l;
    }
}

// comb = x_t + h_{t-1}: fp32 into g_G part0 + bf16 hi/lo planes
__global__ void add_comb(const float* __restrict__ xt, const float* __restrict__ h, int addH) {
    size_t i = ((size_t)blockIdx.x * blockDim.x + threadIdx.x) * 4;
    float4 v = *reinterpret_cast<const float4*>(xt + i);
    if (addH) {
        float4 hv = *reinterpret_cast<const float4*>(h + i);
        v.x += hv.x; v.y += hv.y; v.z += hv.z; v.w += hv.w;
    }
    *reinterpret_cast<float4*>(g_G + i) = v;
    float hx = __bfloat162float(__float2bfloat16(v.x));
    float hy = __bfloat162float(__float2bfloat16(v.y));
    float hz = __bfloat162float(__float2bfloat16(v.z));
    float hw = __bfloat162float(__float2bfloat16(v.w));
    uint2 hp = make_uint2(packbf2(v.x, v.y), packbf2(v.z, v.w));
    uint2 lp = make_uint2(packbf2(v.x - hx, v.y - hy), packbf2(v.z - hz, v.w - hw));
    *reinterpret_cast<uint2*>(g_combhi + i) = hp;
    *reinterpret_cast<uint2*>(g_comblo + i) = lp;
}

// ---------------------------------------------------------------------------
// Hop GEMM via mma.sync bf16 split-3.
// C(2048x1024) = A(2048x1024) @ support(1024x1024)
// CTA 128x128, CHUNK_K=32, double-buffered cp.async SMEM.
// SMEM row stride 80B (40 bf16) -> conflict-free 32b fragment loads.
#define ROWB 80
#define PLANE 10240                 // 128 rows * 80B
#define BUFB  (4*PLANE)             // Ahi|Alo|Bhi|Blo
#define HOP_SMEM (2*BUFB)           // 81920

__global__ __launch_bounds__(256, 1) void hop_mma(
    const __nv_bfloat16* __restrict__ Ahi, const __nv_bfloat16* __restrict__ Alo,
    float* __restrict__ Cout,
    __nv_bfloat16* __restrict__ Chi, __nv_bfloat16* __restrict__ Clo, int writeSplit)
{
    extern __shared__ char smem[];
    uint32_t sb = smem_to_u32(smem);
    const int tid = threadIdx.x, lane = tid & 31, wid = tid >> 5;
    const int wm = wid & 3, wn = wid >> 2;          // warp tile: M32 x N64
    const int m0 = blockIdx.y * 128, n0 = blockIdx.x * 128;
    const int lr  = lane >> 2;                      // 0..7
    const int lc4 = (lane & 3) * 4;                 // pair byte offset in k16

    float acc[2][8][4];
    #pragma unroll
    for (int mt = 0; mt < 2; mt++)
        #pragma unroll
        for (int nt = 0; nt < 8; nt++)
            #pragma unroll
            for (int q = 0; q < 4; q++) acc[mt][nt][q] = 0.f;

    // global load: idx -> row (0..127), c16 (0..3) 16B within 64B k-chunk row
    const int gr  = tid >> 2, gc = tid & 3;

    // prologue: chunk 0 -> buf 0
    {
        uint32_t base = sb;
        #pragma unroll
        for (int it = 0; it < 2; it++) {
            int row = gr + it * 64;
            uint32_t doff = (uint32_t)(row * ROWB + gc * 16);
            size_t ga = (((size_t)(m0 + row)) << 10) + gc * 8;
            size_t gb = (((size_t)(n0 + row)) << 10) + gc * 8;
            cpasync16(base + doff,             Ahi   + ga);
            cpasync16(base + PLANE + doff,     Alo   + ga);
            cpasync16(base + 2 * PLANE + doff, g_Bhi + gb);
            cpasync16(base + 3 * PLANE + doff, g_Blo + gb);
        }
        CP_COMMIT();
    }

    for (int chunk = 0; chunk < 32; chunk++) {
        uint32_t base = sb + (chunk & 1) * BUFB;
        if (chunk + 1 < 32) {
            uint32_t nbase = sb + ((chunk + 1) & 1) * BUFB;
            int k0 = (chunk + 1) * 32;
            #pragma unroll
            for (int it = 0; it < 2; it++) {
                int row = gr + it * 64;
                uint32_t doff = (uint32_t)(row * ROWB + gc * 16);
                size_t ga = (((size_t)(m0 + row)) << 10) + k0 + gc * 8;
                size_t gb = (((size_t)(n0 + row)) << 10) + k0 + gc * 8;
                cpasync16(nbase + doff,             Ahi   + ga);
                cpasync16(nbase + PLANE + doff,     Alo   + ga);
                cpasync16(nbase + 2 * PLANE + doff, g_Bhi + gb);
                cpasync16(nbase + 3 * PLANE + doff, g_Blo + gb);
            }
            CP_COMMIT();
            CP_WAIT(1);
        } else {
            CP_WAIT(0);
        }
        __syncthreads();

        uint32_t aB = base + (uint32_t)(wm * 32) * ROWB;
        uint32_t bB = base + 2 * PLANE + (uint32_t)(wn * 64) * ROWB;
        #pragma unroll
        for (int ks = 0; ks < 2; ks++) {
            uint32_t koff = (uint32_t)(ks * 32 + lc4);
            uint32_t ah[2][4], al[2][4];
            #pragma unroll
            for (int mt = 0; mt < 2; mt++) {
                uint32_t r0 = aB + (uint32_t)((mt * 16 + lr) * ROWB) + koff;
                ah[mt][0] = lds32(r0);
                ah[mt][1] = lds32(r0 + 8 * ROWB);
                ah[mt][2] = lds32(r0 + 16);
                ah[mt][3] = lds32(r0 + 8 * ROWB + 16);
                al[mt][0] = lds32(r0 + PLANE);
                al[mt][1] = lds32(r0 + PLANE + 8 * ROWB);
                al[mt][2] = lds32(r0 + PLANE + 16);
                al[mt][3] = lds32(r0 + PLANE + 8 * ROWB + 16);
            }
            uint32_t bh[8][2], bl[8][2];
            #pragma unroll
            for (int nt = 0; nt < 8; nt++) {
                uint32_t r0 = bB + (uint32_t)((nt * 8 + lr) * ROWB) + koff;
                bh[nt][0] = lds32(r0);
                bh[nt][1] = lds32(r0 + 16);
                bl[nt][0] = lds32(r0 + PLANE);
                bl[nt][1] = lds32(r0 + PLANE + 16);
            }
            #pragma unroll
            for (int mt = 0; mt < 2; mt++)
                #pragma unroll
                for (int nt = 0; nt < 8; nt++) {
                    mma16816(acc[mt][nt], ah[mt], bh[nt]);
                    mma16816(acc[mt][nt], ah[mt], bl[nt]);
                    mma16816(acc[mt][nt], al[mt], bh[nt]);
                }
        }
        __syncthreads();
    }

    // Epilogue: fp32 C (+ optional bf16 hi/lo planes)
    #pragma unroll
    for (int mt = 0; mt < 2; mt++) {
        int row = m0 + wm * 32 + mt * 16 + lr;
        #pragma unroll
        for (int nt = 0; nt < 8; nt++) {
            int col = n0 + wn * 64 + nt * 8 + (lane & 3) * 2;
            float* c0 = Cout + (size_t)row * 1024 + col;
            float* c1 = Cout + (size_t)(row + 8) * 1024 + col;
            *reinterpret_cast<float2*>(c0) = make_float2(acc[mt][nt][0], acc[mt][nt][1]);
            *reinterpret_cast<float2*>(c1) = make_float2(acc[mt][nt][2], acc[mt][nt][3]);
            if (writeSplit) {
                float v0 = acc[mt][nt][0], v1 = acc[mt][nt][1];
                float v2 = acc[mt][nt][2], v3 = acc[mt][nt][3];
                float h0 = __bfloat162float(__float2bfloat16(v0));
                float h1 = __bfloat162float(__float2bfloat16(v1));
                float h2 = __bfloat162float(__float2bfloat16(v2));
                float h3 = __bfloat162float(__float2bfloat16(v3));
                size_t o0 = (size_t)row * 1024 + col;
                size_t o1 = (size_t)(row + 8) * 1024 + col;
                *reinterpret_cast<uint32_t*>(Chi + o0) = packbf2(v0, v1);
                *reinterpret_cast<uint32_t*>(Chi + o1) = packbf2(v2, v3);
                *reinterpret_cast<uint32_t*>(Clo + o0) = packbf2(v0 - h0, v1 - h1);
                *reinterpret_cast<uint32_t*>(Clo + o1) = packbf2(v2 - h2, v3 - h3);
            }
        }
    }
}

// ---------------------------------------------------------------------------
// Fused gate GEMM + LSTM pointwise (fp32, proven)
#define BPAD 68
#define WPAD 260
__global__ __launch_bounds__(256, 2) void gate_lstm(
    const float* __restrict__ W, const float* __restrict__ bias,
    float* __restrict__ ysOut)
{
    __shared__ float As[8 * WPAD];
    __shared__ float Bs[8 * BPAD];

    int tid = threadIdx.x;
    int bx = blockIdx.x;
    int b  = blockIdx.y;

    const float* Wrow = W + (size_t)tid * 192;
    int bRow = tid >> 4;
    int bCol = (tid & 15) * 4;
    int c0   = (tid >> 3) * 2;
    int tCol = (tid & 7) * 8;

    float acc[8][8];
    #pragma unroll
    for (int r = 0; r < 8; r++)
        #pragma unroll
        for (int j = 0; j < 8; j++) acc[r][j] = 0.f;

    auto rowptr = [&](int k) -> const float* {
        return g_G + (size_t)(k >> 6) * PART + (size_t)b * CVSZ +
               (size_t)(k & 63) * VV + bx * 64;
    };

    float4 w0 = *reinterpret_cast<const float4*>(Wrow + 0);
    float4 w1 = *reinterpret_cast<const float4*>(Wrow + 4);
    float4 b4 = make_float4(0.f, 0.f, 0.f, 0.f);
    if (tid < 128)
        b4 = *reinterpret_cast<const float4*>(rowptr(bRow) + bCol);

    for (int k0 = 0; k0 < 192; k0 += 8) {
        As[0 * WPAD + tid] = w0.x;
        As[1 * WPAD + tid] = w0.y;
        As[2 * WPAD + tid] = w0.z;
        As[3 * WPAD + tid] = w0.w;
        As[4 * WPAD + tid] = w1.x;
        As[5 * WPAD + tid] = w1.y;
        As[6 * WPAD + tid] = w1.z;
        As[7 * WPAD + tid] = w1.w;
        if (tid < 128)
            *reinterpret_cast<float4*>(&Bs[bRow * BPAD + bCol]) = b4;
        __syncthreads();

        if (k0 + 8 < 192) {
            w0 = *reinterpret_cast<const float4*>(Wrow + k0 + 8);
            w1 = *reinterpret_cast<const float4*>(Wrow + k0 + 12);
            if (tid < 128)
                b4 = *reinterpret_cast<const float4*>(rowptr(k0 + 8 + bRow) + bCol);
        }

        #pragma unroll
        for (int k = 0; k < 8; k++) {
            float regM[8];
            #pragma unroll
            for (int g = 0; g < 4; g++) {
                float2 m = *reinterpret_cast<const float2*>(&As[k * WPAD + g * 64 + c0]);
                regM[g * 2 + 0] = m.x;
                regM[g * 2 + 1] = m.y;
            }
            float4 rn0 = *reinterpret_cast<const float4*>(&Bs[k * BPAD + tCol]);
            float4 rn1 = *reinterpret_cast<const float4*>(&Bs[k * BPAD + tCol + 4]);
            float regN[8] = {rn0.x, rn0.y, rn0.z, rn0.w, rn1.x, rn1.y, rn1.z, rn1.w};
            #pragma unroll
            for (int r = 0; r < 8; r++)
                #pragma unroll
                for (int j = 0; j < 8; j++) acc[r][j] += regM[r] * regN[j];
        }
        __syncthreads();
    }

    #pragma unroll
    for (int p = 0; p < 2; p++) {
        int c = c0 + p;
        float bi = bias[c];
        float bf = bias[64 + c];
        float bg = bias[128 + c];
        float bo = bias[192 + c];
        size_t base = (size_t)b * CVSZ + (size_t)c * VV + bx * 64 + tCol;

        float4 cold0 = *reinterpret_cast<const float4*>(g_c + base);
        float4 cold1 = *reinterpret_cast<const float4*>(g_c + base + 4);
        float coldv[8] = {cold0.x, cold0.y, cold0.z, cold0.w,
                          cold1.x, cold1.y, cold1.z, cold1.w};
        float cy[8], hy[8];
        #pragma unroll
        for (int j = 0; j < 8; j++) {
            float ig = acc[0 * 2 + p][j] + bi;
            float fg = acc[1 * 2 + p][j] + bf;
            float gg = acc[2 * 2 + p][j] + bg;
            float og = acc[3 * 2 + p][j] + bo;
            float ccur = sigf(fg) * coldv[j] + sigf(ig) * gg;
            cy[j] = ccur;
            hy[j] = sigf(og) * tanh_fast(ccur);
        }
        *reinterpret_cast<float4*>(g_c + base)     = make_float4(cy[0], cy[1], cy[2], cy[3]);
        *reinterpret_cast<float4*>(g_c + base + 4) = make_float4(cy[4], cy[5], cy[6], cy[7]);
        *reinterpret_cast<float4*>(ysOut + base)     = make_float4(hy[0], hy[1], hy[2], hy[3]);
        *reinterpret_cast<float4*>(ysOut + base + 4) = make_float4(hy[4], hy[5], hy[6], hy[7]);
    }
}

// ---------------------------------------------------------------------------
__global__ __launch_bounds__(256) void proj_out(const float* __restrict__ Wout,
                                                const float* __restrict__ bout,
                                                float* __restrict__ out) {
    __shared__ float sm[TT * CC * 8];
    int b  = blockIdx.y;
    int v0 = blockIdx.x * 8;
    for (int i = threadIdx.x; i < TT * CC * 8; i += 256) {
        int t = i / (CC * 8);
        int rem = i % (CC * 8);
        int c = rem >> 3, vv = rem & 7;
        sm[i] = g_ys[(size_t)t * PART + (size_t)b * CVSZ + (size_t)c * VV + v0 + vv];
    }
    __syncthreads();
    for (int p = threadIdx.x; p < COUT * 8; p += 256) {
        int o = p >> 3, vv = p & 7;
        float accp[TT];
        #pragma unroll
        for (int t = 0; t < TT; t++) accp[t] = 0.f;
        for (int c = 0; c < CC; c++) {
            float w = Wout[o * CC + c];
            #pragma unroll
            for (int t = 0; t < TT; t++) accp[t] += w * sm[t * (CC * 8) + c * 8 + vv];
        }
        float bo = bout[o];
        float* op = out + ((size_t)(b * COUT + o) * VV + v0 + vv) * TT;
        #pragma unroll
        for (int t = 0; t < TT; t++) op[t] = accp[t] + bo;
    }
}

// ---------------------------------------------------------------------------
extern "C" void kernel_launch(void* const* d_in, const int* in_sizes, int n_in,
                              void* d_out, int out_size) {
    const float* x      = (const float*)d_in[0];
    const float* Amat   = (const float*)d_in[1];
    const float* W_gout = (const float*)d_in[2];
    const float* b_gout = (const float*)d_in[3];
    const float* W_out  = (const float*)d_in[4];
    const float* b_out  = (const float*)d_in[5];
    float* out = (float*)d_out;

    float *xT, *ys, *G;
    __nv_bfloat16 *chi, *clo, *x1hi, *x1lo;
    cudaGetSymbolAddress((void**)&xT, g_xT);
    cudaGetSymbolAddress((void**)&ys, g_ys);
    cudaGetSymbolAddress((void**)&G,  g_G);
    cudaGetSymbolAddress((void**)&chi,  g_combhi);
    cudaGetSymbolAddress((void**)&clo,  g_comblo);
    cudaGetSymbolAddress((void**)&x1hi, g_x1hi);
    cudaGetSymbolAddress((void**)&x1lo, g_x1lo);

    cudaFuncSetAttribute(hop_mma, cudaFuncAttributeMaxDynamicSharedMemorySize, HOP_SMEM);

    transpose_x<<<dim3(MROWS, VV / 32), 256>>>(x);
    zero_c<<<(MROWS * VV) / 256, 256>>>();
    bsplit<<<dim3(32, 32), 256>>>(Amat);

    dim3 hopGrid(VV / 128, MROWS / 128);   // (8, 16) = 128 CTAs
    dim3 gateGrid(VV / 64, BB);            // (16, 32)

    for (int t = 0; t < TT; t++) {
        const float* hprev = (t > 0) ? (ys + (size_t)(t - 1) * PART) : ys;
        add_comb<<<(MROWS * VV / 4) / 256, 256>>>(xT + (size_t)t * PART, hprev, t > 0 ? 1 : 0);
        // x1 = comb @ A  (fp32 -> g_G part1, bf16 planes for hop2)
        hop_mma<<<hopGrid, 256, HOP_SMEM>>>(chi, clo, G + PART, x1hi, x1lo, 1);
        // x2 = x1 @ A   (fp32 -> g_G part2)
        hop_mma<<<hopGrid, 256, HOP_SMEM>>>(x1hi, x1lo, G + 2 * PART, nullptr, nullptr, 0);
        gate_lstm<<<gateGrid, 256>>>(W_gout, b_gout, ys + (size_t)t * PART);
    }

    proj_out<<<dim3(VV / 8, BB), 256>>>(W_out, b_out, out);
}

// round 5
// speedup vs baseline: 2.3412x; 1.3017x over previous
#include <cuda_runtime.h>
#include <cuda_bf16.h>
#include <math.h>
#include <stdint.h>

// Problem constants
#define BB 32
#define CC 64
#define VV 1024
#define TT 24
#define COUT 64
#define MROWS (BB*CC)            // 2048
#define PART ((size_t)MROWS*VV)  // 2,097,152 floats
#define CVSZ (CC*VV)             // 65536

// ---------------------------------------------------------------------------
__device__ __forceinline__ uint32_t smem_to_u32(const void* p) {
    uint32_t a;
    asm("{ .reg .u64 t; cvta.to.shared.u64 t, %1; cvt.u32.u64 %0, t; }" : "=r"(a) : "l"(p));
    return a;
}
__device__ __forceinline__ uint32_t lds32(uint32_t a) {
    uint32_t v; asm("ld.shared.b32 %0, [%1];" : "=r"(v) : "r"(a)); return v;
}
__device__ __forceinline__ void cpasync16(uint32_t dst, const void* src) {
    asm volatile("cp.async.cg.shared.global [%0], [%1], 16;" :: "r"(dst), "l"(src));
}
#define CP_COMMIT() asm volatile("cp.async.commit_group;" ::: "memory")
#define CP_WAIT(n)  asm volatile("cp.async.wait_group %0;" :: "n"(n) : "memory")

__device__ __forceinline__ void ldsm_x4(uint32_t* r, uint32_t a) {
    asm volatile("ldmatrix.sync.aligned.m8n8.x4.shared.b16 {%0,%1,%2,%3}, [%4];"
                 : "=r"(r[0]), "=r"(r[1]), "=r"(r[2]), "=r"(r[3]) : "r"(a));
}
__device__ __forceinline__ void ldsm_x4_trans(uint32_t* r, uint32_t a) {
    asm volatile("ldmatrix.sync.aligned.m8n8.x4.trans.shared.b16 {%0,%1,%2,%3}, [%4];"
                 : "=r"(r[0]), "=r"(r[1]), "=r"(r[2]), "=r"(r[3]) : "r"(a));
}

// m16n8k16 row.col bf16 -> fp32 accumulate (baseline PTX, works on sm_103)
__device__ __forceinline__ void mma16816(float* c, const uint32_t* a, const uint32_t* b) {
    asm volatile(
        "mma.sync.aligned.m16n8k16.row.col.f32.bf16.bf16.f32 "
        "{%0,%1,%2,%3}, {%4,%5,%6,%7}, {%8,%9}, {%0,%1,%2,%3};"
        : "+f"(c[0]), "+f"(c[1]), "+f"(c[2]), "+f"(c[3])
        : "r"(a[0]), "r"(a[1]), "r"(a[2]), "r"(a[3]), "r"(b[0]), "r"(b[1]));
}

__device__ __forceinline__ float sigf(float x) { return 1.0f / (1.0f + __expf(-x)); }
__device__ __forceinline__ float tanh_fast(float x) {
    float y; asm("tanh.approx.f32 %0, %1;" : "=f"(y) : "f"(x)); return y;
}
__device__ __forceinline__ uint32_t packbf2(float a, float b) {
    return ((uint32_t)__bfloat16_as_ushort(__float2bfloat16(b)) << 16) |
           (uint32_t)__bfloat16_as_ushort(__float2bfloat16(a));
}

// ---------------------------------------------------------------------------
// Scratch
__device__ __align__(128) float g_xT[(size_t)TT*MROWS*VV];
__device__ __align__(128) float g_ys[(size_t)TT*MROWS*VV];
__device__ __align__(128) float g_c[(size_t)MROWS*VV];
__device__ __align__(128) __nv_bfloat16 g_combhi[(size_t)MROWS*VV];
__device__ __align__(128) __nv_bfloat16 g_comblo[(size_t)MROWS*VV];
__device__ __align__(128) __nv_bfloat16 g_x1hi[(size_t)MROWS*VV];
__device__ __align__(128) __nv_bfloat16 g_x1lo[(size_t)MROWS*VV];
__device__ __align__(128) __nv_bfloat16 g_x2hi[(size_t)MROWS*VV];
__device__ __align__(128) __nv_bfloat16 g_x2lo[(size_t)MROWS*VV];
__device__ __align__(128) __nv_bfloat16 g_Bhi[(size_t)VV*VV];  // A^T hi  [n][k]
__device__ __align__(128) __nv_bfloat16 g_Blo[(size_t)VV*VV];  // A^T lo  [n][k]
__device__ __align__(128) __nv_bfloat16 g_Whi[256*192];        // permuted W hi [p][k]
__device__ __align__(128) __nv_bfloat16 g_Wlo[256*192];        // permuted W lo [p][k]

// ---------------------------------------------------------------------------
__global__ void transpose_x(const float* __restrict__ x) {
    __shared__ float tile[32][25];
    int r  = blockIdx.x;
    int v0 = blockIdx.y * 32;
    const float* src = x + ((size_t)r * VV + v0) * TT;
    for (int i = threadIdx.x; i < 32 * TT; i += blockDim.x) {
        int v = i / TT, t = i % TT;
        tile[v][t] = src[i];
    }
    __syncthreads();
    for (int i = threadIdx.x; i < 32 * TT; i += blockDim.x) {
        int t = i / 32, v = i % 32;
        g_xT[(size_t)t * PART + (size_t)r * VV + v0 + v] = tile[v][t];
    }
}

__global__ void zero_c() {
    size_t i = (size_t)blockIdx.x * blockDim.x + threadIdx.x;
    g_c[i] = 0.0f;
}

// Bhi/Blo[n][k] = bf16split(A[k][n])
__global__ void bsplit(const float* __restrict__ A) {
    __shared__ float tile[32][33];
    int k0 = blockIdx.x * 32, n0 = blockIdx.y * 32;
    int tx = threadIdx.x & 31, ty = threadIdx.x >> 5;
    #pragma unroll
    for (int i = 0; i < 4; i++) {
        int k = ty + i * 8;
        tile[k][tx] = A[(size_t)(k0 + k) * VV + n0 + tx];
    }
    __syncthreads();
    #pragma unroll
    for (int i = 0; i < 4; i++) {
        int n = ty + i * 8;
        float v = tile[tx][n];
        __nv_bfloat16 h = __float2bfloat16(v);
        __nv_bfloat16 l = __float2bfloat16(v - __bfloat162float(h));
        g_Bhi[(size_t)(n0 + n) * VV + k0 + tx] = h;
        g_Blo[(size_t)(n0 + n) * VV + k0 + tx] = l;
    }
}

// Permuted W split: p = wm*64 + g*16 + cl  <->  o = g*64 + wm*16 + cl
__global__ void wsplit(const float* __restrict__ W) {
    int p = blockIdx.x;           // 0..255
    int k = threadIdx.x;          // 0..191
    int wm = p >> 6, g = (p >> 4) & 3, cl = p & 15;
    int o = g * 64 + wm * 16 + cl;
    float v = W[(size_t)o * 192 + k];
    __nv_bfloat16 h = __float2bfloat16(v);
    __nv_bfloat16 l = __float2bfloat16(v - __bfloat162float(h));
    g_Whi[p * 192 + k] = h;
    g_Wlo[p * 192 + k] = l;
}

// comb = x_t + h_{t-1}: bf16 hi/lo planes only
__global__ void add_comb(const float* __restrict__ xt, const float* __restrict__ h, int addH) {
    size_t i = ((size_t)blockIdx.x * blockDim.x + threadIdx.x) * 4;
    float4 v = *reinterpret_cast<const float4*>(xt + i);
    if (addH) {
        float4 hv = *reinterpret_cast<const float4*>(h + i);
        v.x += hv.x; v.y += hv.y; v.z += hv.z; v.w += hv.w;
    }
    float hx = __bfloat162float(__float2bfloat16(v.x));
    float hy = __bfloat162float(__float2bfloat16(v.y));
    float hz = __bfloat162float(__float2bfloat16(v.z));
    float hw = __bfloat162float(__float2bfloat16(v.w));
    uint2 hp = make_uint2(packbf2(v.x, v.y), packbf2(v.z, v.w));
    uint2 lp = make_uint2(packbf2(v.x - hx, v.y - hy), packbf2(v.z - hz, v.w - hw));
    *reinterpret_cast<uint2*>(g_combhi + i) = hp;
    *reinterpret_cast<uint2*>(g_comblo + i) = lp;
}

// ---------------------------------------------------------------------------
// Hop GEMM via mma.sync bf16 split-3. Output: bf16 hi/lo planes only.
#define ROWB 80
#define PLANE 10240                 // 128 rows * 80B
#define BUFB  (4*PLANE)
#define HOP_SMEM (2*BUFB)           // 81920

__global__ __launch_bounds__(256, 1) void hop_mma(
    const __nv_bfloat16* __restrict__ Ahi, const __nv_bfloat16* __restrict__ Alo,
    __nv_bfloat16* __restrict__ Chi, __nv_bfloat16* __restrict__ Clo)
{
    extern __shared__ char smem[];
    uint32_t sb = smem_to_u32(smem);
    const int tid = threadIdx.x, lane = tid & 31, wid = tid >> 5;
    const int wm = wid & 3, wn = wid >> 2;          // warp tile: M32 x N64
    const int m0 = blockIdx.y * 128, n0 = blockIdx.x * 128;
    const int lr  = lane >> 2;
    const int lc4 = (lane & 3) * 4;

    float acc[2][8][4];
    #pragma unroll
    for (int mt = 0; mt < 2; mt++)
        #pragma unroll
        for (int nt = 0; nt < 8; nt++)
            #pragma unroll
            for (int q = 0; q < 4; q++) acc[mt][nt][q] = 0.f;

    const int gr = tid >> 2, gc = tid & 3;

    {
        uint32_t base = sb;
        #pragma unroll
        for (int it = 0; it < 2; it++) {
            int row = gr + it * 64;
            uint32_t doff = (uint32_t)(row * ROWB + gc * 16);
            size_t ga = (((size_t)(m0 + row)) << 10) + gc * 8;
            size_t gb = (((size_t)(n0 + row)) << 10) + gc * 8;
            cpasync16(base + doff,             Ahi   + ga);
            cpasync16(base + PLANE + doff,     Alo   + ga);
            cpasync16(base + 2 * PLANE + doff, g_Bhi + gb);
            cpasync16(base + 3 * PLANE + doff, g_Blo + gb);
        }
        CP_COMMIT();
    }

    for (int chunk = 0; chunk < 32; chunk++) {
        uint32_t base = sb + (chunk & 1) * BUFB;
        if (chunk + 1 < 32) {
            uint32_t nbase = sb + ((chunk + 1) & 1) * BUFB;
            int k0 = (chunk + 1) * 32;
            #pragma unroll
            for (int it = 0; it < 2; it++) {
                int row = gr + it * 64;
                uint32_t doff = (uint32_t)(row * ROWB + gc * 16);
                size_t ga = (((size_t)(m0 + row)) << 10) + k0 + gc * 8;
                size_t gb = (((size_t)(n0 + row)) << 10) + k0 + gc * 8;
                cpasync16(nbase + doff,             Ahi   + ga);
                cpasync16(nbase + PLANE + doff,     Alo   + ga);
                cpasync16(nbase + 2 * PLANE + doff, g_Bhi + gb);
                cpasync16(nbase + 3 * PLANE + doff, g_Blo + gb);
            }
            CP_COMMIT();
            CP_WAIT(1);
        } else {
            CP_WAIT(0);
        }
        __syncthreads();

        uint32_t aB = base + (uint32_t)(wm * 32) * ROWB;
        uint32_t bB = base + 2 * PLANE + (uint32_t)(wn * 64) * ROWB;
        #pragma unroll
        for (int ks = 0; ks < 2; ks++) {
            uint32_t koff = (uint32_t)(ks * 32 + lc4);
            uint32_t ah[2][4], al[2][4];
            #pragma unroll
            for (int mt = 0; mt < 2; mt++) {
                uint32_t r0 = aB + (uint32_t)((mt * 16 + lr) * ROWB) + koff;
                ah[mt][0] = lds32(r0);
                ah[mt][1] = lds32(r0 + 8 * ROWB);
                ah[mt][2] = lds32(r0 + 16);
                ah[mt][3] = lds32(r0 + 8 * ROWB + 16);
                al[mt][0] = lds32(r0 + PLANE);
                al[mt][1] = lds32(r0 + PLANE + 8 * ROWB);
                al[mt][2] = lds32(r0 + PLANE + 16);
                al[mt][3] = lds32(r0 + PLANE + 8 * ROWB + 16);
            }
            uint32_t bh[8][2], bl[8][2];
            #pragma unroll
            for (int nt = 0; nt < 8; nt++) {
                uint32_t r0 = bB + (uint32_t)((nt * 8 + lr) * ROWB) + koff;
                bh[nt][0] = lds32(r0);
                bh[nt][1] = lds32(r0 + 16);
                bl[nt][0] = lds32(r0 + PLANE);
                bl[nt][1] = lds32(r0 + PLANE + 16);
            }
            #pragma unroll
            for (int mt = 0; mt < 2; mt++)
                #pragma unroll
                for (int nt = 0; nt < 8; nt++) {
                    mma16816(acc[mt][nt], ah[mt], bh[nt]);
                    mma16816(acc[mt][nt], ah[mt], bl[nt]);
                    mma16816(acc[mt][nt], al[mt], bh[nt]);
                }
        }
        __syncthreads();
    }

    // Epilogue: bf16 hi/lo planes
    #pragma unroll
    for (int mt = 0; mt < 2; mt++) {
        int row = m0 + wm * 32 + mt * 16 + lr;
        #pragma unroll
        for (int nt = 0; nt < 8; nt++) {
            int col = n0 + wn * 64 + nt * 8 + (lane & 3) * 2;
            float v0 = acc[mt][nt][0], v1 = acc[mt][nt][1];
            float v2 = acc[mt][nt][2], v3 = acc[mt][nt][3];
            float h0 = __bfloat162float(__float2bfloat16(v0));
            float h1 = __bfloat162float(__float2bfloat16(v1));
            float h2 = __bfloat162float(__float2bfloat16(v2));
            float h3 = __bfloat162float(__float2bfloat16(v3));
            size_t o0 = (size_t)row * 1024 + col;
            size_t o1 = (size_t)(row + 8) * 1024 + col;
            *reinterpret_cast<uint32_t*>(Chi + o0) = packbf2(v0, v1);
            *reinterpret_cast<uint32_t*>(Chi + o1) = packbf2(v2, v3);
            *reinterpret_cast<uint32_t*>(Clo + o0) = packbf2(v0 - h0, v1 - h1);
            *reinterpret_cast<uint32_t*>(Clo + o1) = packbf2(v2 - h2, v3 - h3);
        }
    }
}

// ---------------------------------------------------------------------------
// Tensorized gate GEMM + fused LSTM.
// Per (b, v-tile of 64): gates(256 x 64) = W'(256x192) @ G_b(192x64) + bias.
// W rows permuted so m16-tile index == gate index -> LSTM in registers.
#define RKW 80
#define RKG 144
#define WS_PLANE (256*RKW)                       // 20480
#define GS_PLANE (32*RKG)                        // 4608
#define GATE_CHUNK (2*WS_PLANE + 2*GS_PLANE)     // 50176
#define GATE_SMEM (2*GATE_CHUNK)                 // 100352

__global__ __launch_bounds__(256) void gate_lstm_mma(
    const float* __restrict__ bias, float* __restrict__ ysOut)
{
    extern __shared__ char smem[];
    uint32_t sb = smem_to_u32(smem);
    const int tid = threadIdx.x, lane = tid & 31, wid = tid >> 5;
    const int wm = wid & 3, wn = wid >> 2;       // warp tile M64 x N32
    const int v0 = blockIdx.x * 64;
    const int b  = blockIdx.y;
    const int grp = lane >> 3, lr8 = lane & 7;

    const __nv_bfloat16* GHI[3] = {g_combhi, g_x1hi, g_x2hi};
    const __nv_bfloat16* GLO[3] = {g_comblo, g_x1lo, g_x2lo};

    float acc[4][4][4];
    #pragma unroll
    for (int mt = 0; mt < 4; mt++)
        #pragma unroll
        for (int nt = 0; nt < 4; nt++)
            #pragma unroll
            for (int q = 0; q < 4; q++) acc[mt][nt][q] = 0.f;

    // chunk loader: ck in 0..5 (k = 32*ck .. 32*ck+31)
    auto load_chunk = [&](int ck, uint32_t base) {
        // W planes: thread tid = row p, 4 x 16B
        const __nv_bfloat16* wh = g_Whi + (size_t)tid * 192 + ck * 32;
        const __nv_bfloat16* wl = g_Wlo + (size_t)tid * 192 + ck * 32;
        uint32_t wd = base + (uint32_t)tid * RKW;
        #pragma unroll
        for (int q = 0; q < 4; q++) {
            cpasync16(wd + q * 16,            wh + q * 8);
            cpasync16(wd + WS_PLANE + q * 16, wl + q * 8);
        }
        // G planes: 32 rows x 128B; thread: kl = tid>>3, i = tid&7
        int plane = ck >> 1, coff = (ck & 1) * 32;
        int kl = tid >> 3, i8 = tid & 7;
        size_t gsrc = (((size_t)(b * 64 + coff + kl)) << 10) + v0 + i8 * 8;
        uint32_t gd = base + 2 * WS_PLANE + (uint32_t)(kl * RKG + i8 * 16);
        cpasync16(gd,            GHI[plane] + gsrc);
        cpasync16(gd + GS_PLANE, GLO[plane] + gsrc);
        CP_COMMIT();
    };

    load_chunk(0, sb);

    for (int ck = 0; ck < 6; ck++) {
        uint32_t base = sb + (ck & 1) * GATE_CHUNK;
        if (ck + 1 < 6) {
            load_chunk(ck + 1, sb + ((ck + 1) & 1) * GATE_CHUNK);
            CP_WAIT(1);
        } else {
            CP_WAIT(0);
        }
        __syncthreads();

        #pragma unroll
        for (int ks = 0; ks < 2; ks++) {
            // A fragments (W, non-trans ldmatrix)
            uint32_t ah[4][4], al[4][4];
            #pragma unroll
            for (int mt = 0; mt < 4; mt++) {
                uint32_t a = base +
                    (uint32_t)((wm * 64 + mt * 16 + (grp & 1) * 8 + lr8) * RKW) +
                    (uint32_t)(ks * 32 + (grp >> 1) * 16);
                ldsm_x4(ah[mt], a);
                ldsm_x4(al[mt], a + WS_PLANE);
            }
            // B fragments (G, trans ldmatrix): two x4 per plane cover n0-15, n16-31
            uint32_t bh[4][2], bl[4][2];
            #pragma unroll
            for (int h = 0; h < 2; h++) {
                uint32_t a = base + 2 * WS_PLANE +
                    (uint32_t)((ks * 16 + (grp & 1) * 8 + lr8) * RKG) +
                    (uint32_t)(wn * 64 + h * 32 + (grp >> 1) * 16);
                uint32_t r[4];
                ldsm_x4_trans(r, a);
                bh[2 * h][0] = r[0]; bh[2 * h][1] = r[1];
                bh[2 * h + 1][0] = r[2]; bh[2 * h + 1][1] = r[3];
                ldsm_x4_trans(r, a + GS_PLANE);
                bl[2 * h][0] = r[0]; bl[2 * h][1] = r[1];
                bl[2 * h + 1][0] = r[2]; bl[2 * h + 1][1] = r[3];
            }
            #pragma unroll
            for (int mt = 0; mt < 4; mt++)
                #pragma unroll
                for (int nt = 0; nt < 4; nt++) {
                    mma16816(acc[mt][nt], ah[mt], bh[nt]);
                    mma16816(acc[mt][nt], ah[mt], bl[nt]);
                    mma16816(acc[mt][nt], al[mt], bh[nt]);
                }
        }
        __syncthreads();
    }

    // Fused LSTM epilogue. gate = mt; c = wm*16 + r + 8s.
    const int r = lane >> 2;
    const int q2 = (lane & 3) * 2;
    #pragma unroll
    for (int s = 0; s < 2; s++) {
        int c = wm * 16 + r + 8 * s;
        float bi = bias[c];
        float bf = bias[64 + c];
        float bg = bias[128 + c];
        float bo = bias[192 + c];
        #pragma unroll
        for (int nt = 0; nt < 4; nt++) {
            int v = v0 + wn * 32 + nt * 8 + q2;
            size_t idx = (size_t)b * CVSZ + (size_t)c * VV + v;
            float2 cold = *reinterpret_cast<const float2*>(g_c + idx);
            float i0 = acc[0][nt][2 * s]     + bi;
            float i1 = acc[0][nt][2 * s + 1] + bi;
            float f0 = acc[1][nt][2 * s]     + bf;
            float f1 = acc[1][nt][2 * s + 1] + bf;
            float g0 = acc[2][nt][2 * s]     + bg;
            float g1 = acc[2][nt][2 * s + 1] + bg;
            float o0 = acc[3][nt][2 * s]     + bo;
            float o1 = acc[3][nt][2 * s + 1] + bo;
            float cy0 = sigf(f0) * cold.x + sigf(i0) * g0;
            float cy1 = sigf(f1) * cold.y + sigf(i1) * g1;
            float hy0 = sigf(o0) * tanh_fast(cy0);
            float hy1 = sigf(o1) * tanh_fast(cy1);
            *reinterpret_cast<float2*>(g_c + idx)   = make_float2(cy0, cy1);
            *reinterpret_cast<float2*>(ysOut + idx) = make_float2(hy0, hy1);
        }
    }
}

// ---------------------------------------------------------------------------
__global__ __launch_bounds__(256) void proj_out(const float* __restrict__ Wout,
                                                const float* __restrict__ bout,
                                                float* __restrict__ out) {
    __shared__ float sm[TT * CC * 8];
    int b  = blockIdx.y;
    int v0 = blockIdx.x * 8;
    for (int i = threadIdx.x; i < TT * CC * 8; i += 256) {
        int t = i / (CC * 8);
        int rem = i % (CC * 8);
        int c = rem >> 3, vv = rem & 7;
        sm[i] = g_ys[(size_t)t * PART + (size_t)b * CVSZ + (size_t)c * VV + v0 + vv];
    }
    __syncthreads();
    for (int p = threadIdx.x; p < COUT * 8; p += 256) {
        int o = p >> 3, vv = p & 7;
        float accp[TT];
        #pragma unroll
        for (int t = 0; t < TT; t++) accp[t] = 0.f;
        for (int c = 0; c < CC; c++) {
            float w = Wout[o * CC + c];
            #pragma unroll
            for (int t = 0; t < TT; t++) accp[t] += w * sm[t * (CC * 8) + c * 8 + vv];
        }
        float bo = bout[o];
        float* op = out + ((size_t)(b * COUT + o) * VV + v0 + vv) * TT;
        #pragma unroll
        for (int t = 0; t < TT; t++) op[t] = accp[t] + bo;
    }
}

// ---------------------------------------------------------------------------
extern "C" void kernel_launch(void* const* d_in, const int* in_sizes, int n_in,
                              void* d_out, int out_size) {
    const float* x      = (const float*)d_in[0];
    const float* Amat   = (const float*)d_in[1];
    const float* W_gout = (const float*)d_in[2];
    const float* b_gout = (const float*)d_in[3];
    const float* W_out  = (const float*)d_in[4];
    const float* b_out  = (const float*)d_in[5];
    float* out = (float*)d_out;

    float *xT, *ys;
    __nv_bfloat16 *chi, *clo, *x1hi, *x1lo, *x2hi, *x2lo;
    cudaGetSymbolAddress((void**)&xT, g_xT);
    cudaGetSymbolAddress((void**)&ys, g_ys);
    cudaGetSymbolAddress((void**)&chi,  g_combhi);
    cudaGetSymbolAddress((void**)&clo,  g_comblo);
    cudaGetSymbolAddress((void**)&x1hi, g_x1hi);
    cudaGetSymbolAddress((void**)&x1lo, g_x1lo);
    cudaGetSymbolAddress((void**)&x2hi, g_x2hi);
    cudaGetSymbolAddress((void**)&x2lo, g_x2lo);

    cudaFuncSetAttribute(hop_mma, cudaFuncAttributeMaxDynamicSharedMemorySize, HOP_SMEM);
    cudaFuncSetAttribute(gate_lstm_mma, cudaFuncAttributeMaxDynamicSharedMemorySize, GATE_SMEM);

    transpose_x<<<dim3(MROWS, VV / 32), 256>>>(x);
    zero_c<<<(MROWS * VV) / 256, 256>>>();
    bsplit<<<dim3(32, 32), 256>>>(Amat);
    wsplit<<<256, 192>>>(W_gout);

    dim3 hopGrid(VV / 128, MROWS / 128);   // (8, 16)
    dim3 gateGrid(VV / 64, BB);            // (16, 32)

    for (int t = 0; t < TT; t++) {
        const float* hprev = (t > 0) ? (ys + (size_t)(t - 1) * PART) : ys;
        add_comb<<<(MROWS * VV / 4) / 256, 256>>>(xT + (size_t)t * PART, hprev, t > 0 ? 1 : 0);
        hop_mma<<<hopGrid, 256, HOP_SMEM>>>(chi, clo, x1hi, x1lo);      // x1 = comb @ A
        hop_mma<<<hopGrid, 256, HOP_SMEM>>>(x1hi, x1lo, x2hi, x2lo);    // x2 = x1 @ A
        gate_lstm_mma<<<gateGrid, 256, GATE_SMEM>>>(b_gout, ys + (size_t)t * PART);
    }

    proj_out<<<dim3(VV / 8, BB), 256>>>(W_out, b_out, out);
}